// round 11
// baseline (speedup 1.0000x reference)
#include <cuda_runtime.h>
#include <cuda_bf16.h>
#include <math.h>
#include <stdint.h>

#define N_NODES 25000
#define N_EDGES 200000
#define E_TOT   (N_EDGES + N_NODES)
#define C_HID   128
#define F_BIG   1024
#define NBLK    ((N_NODES + 1023) / 1024)   // 25

// ---------------- device scratch -------------------------------------------
__device__ __nv_bfloat16  g_hw  [N_NODES * F_BIG];
__device__ __nv_bfloat16  g_act [N_NODES * F_BIG];
__device__ __nv_bfloat16  g_xb  [N_NODES * 64];
__device__ __nv_bfloat16  g_wt1 [1024 * 64];
__device__ __nv_bfloat16  g_wt2 [1024 * 1024];
__device__ __nv_bfloat16  g_wt3 [256 * 1024];    // padded to 256 rows (zeros)
__device__ float          g_bufC[N_NODES * C_HID];
__device__ float g_als [N_NODES * 8];
__device__ float g_ald [N_NODES * 8];
__device__ int   g_src [E_TOT];
__device__ int   g_dst [E_TOT];
__device__ int   g_rowptr[N_NODES + 1];
__device__ int   g_wptr  [N_NODES];
__device__ int   g_csrc  [E_TOT];
__device__ int   g_bsum  [NBLK];
__device__ int   g_sync;

// ---------------- cp.async helpers -----------------------------------------
__device__ __forceinline__ void cpa16(void* sdst, const void* gsrc, int sz) {
    uint32_t sa = (uint32_t)__cvta_generic_to_shared(sdst);
    asm volatile("cp.async.cg.shared.global [%0], [%1], 16, %2;"
                 :: "r"(sa), "l"(gsrc), "r"(sz) : "memory");
}
__device__ __forceinline__ void cpa_commit() {
    asm volatile("cp.async.commit_group;" ::: "memory");
}
template <int W> __device__ __forceinline__ void cpa_wait() {
    asm volatile("cp.async.wait_group %0;" :: "n"(W) : "memory");
}
__device__ __forceinline__ void ldsm_x4(uint32_t& r0, uint32_t& r1,
                                        uint32_t& r2, uint32_t& r3, uint32_t a) {
    asm volatile("ldmatrix.sync.aligned.m8n8.x4.shared.b16 {%0,%1,%2,%3}, [%4];"
                 : "=r"(r0), "=r"(r1), "=r"(r2), "=r"(r3) : "r"(a));
}

// ---------------- fused conversions (+ wptr zeroing, + wt3 pad) -------------
#define SEG0 (N_NODES * 64)
#define SEG1 (SEG0 + 64 * 1024)
#define SEG2 (SEG1 + 1024 * 1024)
#define SEG3 (SEG2 + 1024 * 128)
#define SEG4 (SEG3 + 128 * 1024)
__global__ void cvt_all_k(const float* __restrict__ x,
                          const float* __restrict__ W1,
                          const float* __restrict__ W2,
                          const float* __restrict__ W3) {
    int i = blockIdx.x * blockDim.x + threadIdx.x;
    if (i < N_NODES) g_wptr[i] = 0;
    if (i < SEG0) {
        g_xb[i] = __float2bfloat16(x[i]);
    } else if (i < SEG1) {
        int j = i - SEG0;  int k = j >> 10, n = j & 1023;
        g_wt1[(size_t)n * 64 + k] = __float2bfloat16(W1[j]);
    } else if (i < SEG2) {
        int j = i - SEG1;  int k = j >> 10, n = j & 1023;
        g_wt2[(size_t)n * 1024 + k] = __float2bfloat16(W2[j]);
    } else if (i < SEG3) {
        int j = i - SEG2;  int k = j >> 7, n = j & 127;
        g_wt3[(size_t)n * 1024 + k] = __float2bfloat16(W3[j]);
    } else if (i < SEG4) {
        int j = i - SEG3;
        g_wt3[(size_t)(128 + (j >> 10)) * 1024 + (j & 1023)] = __float2bfloat16(0.f);
    }
}

// ---------------- edge build + histogram (fused) ----------------------------
__global__ void build_hist_k(const int* __restrict__ ei) {
    int i = blockIdx.x * blockDim.x + threadIdx.x;
    if (i == 0) g_sync = 0;
    if (i < N_EDGES) {
        int s = ei[i], d = ei[N_EDGES + i];
        g_src[i] = s;
        g_dst[i] = d;
        atomicAdd(&g_wptr[d], 1);
    } else if (i < E_TOT) {
        int n = i - N_EDGES;
        g_src[i] = n;
        g_dst[i] = n;
        atomicAdd(&g_wptr[n], 1);
    }
}

// ---------------- single-kernel 3-phase scan --------------------------------
__global__ __launch_bounds__(1024) void scan_all_k() {
    __shared__ int ws[32];
    __shared__ int s_off;
    int t = threadIdx.x, lane = t & 31, wid = t >> 5;
    int idx = blockIdx.x * 1024 + t;
    int v = (idx < N_NODES) ? g_wptr[idx] : 0;
    int incl = v;
#pragma unroll
    for (int off = 1; off < 32; off <<= 1) {
        int y = __shfl_up_sync(0xffffffffu, incl, off);
        if (lane >= off) incl += y;
    }
    if (lane == 31) ws[wid] = incl;
    __syncthreads();
    if (wid == 0) {
        int s = ws[lane], si = s;
#pragma unroll
        for (int off = 1; off < 32; off <<= 1) {
            int y = __shfl_up_sync(0xffffffffu, si, off);
            if (lane >= off) si += y;
        }
        ws[lane] = si - s;
    }
    __syncthreads();
    int excl = incl - v + ws[wid];
    if (t == 1023) g_bsum[blockIdx.x] = excl + v;
    __threadfence();
    __syncthreads();
    if (t == 0) {
        atomicAdd(&g_sync, 1);
        while (atomicAdd(&g_sync, 0) < NBLK) {}
    }
    __syncthreads();
    if (t < 32) {
        int v2 = (lane < NBLK) ? g_bsum[lane] : 0;
        int i2 = v2;
#pragma unroll
        for (int off = 1; off < 32; off <<= 1) {
            int y = __shfl_up_sync(0xffffffffu, i2, off);
            if (lane >= off) i2 += y;
        }
        if (lane == (int)blockIdx.x) s_off = i2 - v2;
    }
    __syncthreads();
    int val = excl + s_off;
    if (idx < N_NODES) {
        g_rowptr[idx] = val;
        g_wptr[idx]   = val;
    }
    if (idx == 0) g_rowptr[N_NODES] = E_TOT;
}
__global__ void scatter_k() {
    int e = blockIdx.x * blockDim.x + threadIdx.x;
    if (e < E_TOT) {
        int pos = atomicAdd(&g_wptr[g_dst[e]], 1);
        g_csrc[pos] = g_src[e];
    }
}

// ---------------- bf16 tensor-core GEMM, CTA 128x256, fused att-dots -------
// C[M,N] = A[M,K] @ Bt[Npad,K]^T. 8 warps, warp tile 64x64 (acc 128 regs).
// BK=32, 3 cp.async stages. CTA column spans 2 heads (BN=256).
#define GSTAGES 3
#define T_STRIDE 40
#define ROWS_AB  384                              // 128 A rows + 256 B rows
#define STAGE_ELEMS (ROWS_AB * T_STRIDE)          // 15360
#define STAGE_BYTES (STAGE_ELEMS * 2)             // 30720
#define GEMM_SMEM_BYTES (GSTAGES * STAGE_BYTES)   // 92160

__global__ __launch_bounds__(256, 1) void mma_gemm_k(
    const __nv_bfloat16* __restrict__ A, const __nv_bfloat16* __restrict__ Bt,
    __nv_bfloat16* __restrict__ C, int M, int N, int K,
    const float* __restrict__ a_s, const float* __restrict__ a_d, int H)
{
    extern __shared__ __align__(16) __nv_bfloat16 smem_h[];

    const int t    = threadIdx.x;
    const int bm   = blockIdx.y * 128;
    const int bn   = blockIdx.x * 256;
    const int warp = t >> 5, lane = t & 31;
    const int wm   = (warp >> 2) * 64;
    const int wn   = (warp & 3) * 64;
    const int gid  = lane >> 2;
    const int tg   = lane & 3;

    const int kTiles = K >> 5;

    auto issue_tile = [&](int kt, int st) {
        __nv_bfloat16* base = smem_h + st * STAGE_ELEMS;
#pragma unroll
        for (int q = 0; q < 6; q++) {
            int c = t + q * 256;               // 0..1535
            int row = c >> 2, ce = (c & 3) * 8;
            if (row < 128) {
                int grow = bm + row;
                int sz = (grow < M) ? 16 : 0;
                if (grow >= M) grow = M - 1;
                cpa16(&base[row * T_STRIDE + ce],
                      A + (size_t)grow * K + kt * 32 + ce, sz);
            } else {
                int rb = row - 128;
                cpa16(&base[row * T_STRIDE + ce],
                      Bt + (size_t)(bn + rb) * K + kt * 32 + ce, 16);
            }
        }
    };

    // ldmatrix lane addresses (stage 0, k-step 0)
    const int q = lane >> 3, r = lane & 7;
    const uint32_t s0 = (uint32_t)__cvta_generic_to_shared(smem_h);
    uint32_t a_addr[4], b_addr[4];
#pragma unroll
    for (int mt = 0; mt < 4; mt++) {
        int row = wm + mt * 16 + r + ((q & 1) << 3);
        int col = (q >> 1) << 3;
        a_addr[mt] = s0 + (row * T_STRIDE + col) * 2;
    }
#pragma unroll
    for (int p = 0; p < 4; p++) {
        int row = 128 + wn + ((p * 2 + (q >> 1)) << 3) + r;
        int col = (q & 1) << 3;
        b_addr[p] = s0 + (row * T_STRIDE + col) * 2;
    }

    float acc[4][8][4];
#pragma unroll
    for (int i = 0; i < 4; i++)
#pragma unroll
        for (int j = 0; j < 8; j++)
#pragma unroll
            for (int z = 0; z < 4; z++) acc[i][j][z] = 0.f;

#pragma unroll
    for (int s = 0; s < GSTAGES - 1; s++) {
        if (s < kTiles) issue_tile(s, s);
        cpa_commit();
    }

    for (int kt = 0; kt < kTiles; kt++) {
        cpa_wait<GSTAGES - 2>();
        __syncthreads();

        int nt = kt + GSTAGES - 1;
        if (nt < kTiles) issue_tile(nt, nt % GSTAGES);
        cpa_commit();

        const uint32_t soff = (uint32_t)((kt % GSTAGES) * STAGE_BYTES);

#pragma unroll
        for (int ks = 0; ks < 2; ks++) {
            const uint32_t ko = soff + ks * 32;
            uint32_t af[4][4], bf[8][2];
#pragma unroll
            for (int mt = 0; mt < 4; mt++)
                ldsm_x4(af[mt][0], af[mt][1], af[mt][2], af[mt][3], a_addr[mt] + ko);
#pragma unroll
            for (int p = 0; p < 4; p++)
                ldsm_x4(bf[p * 2][0], bf[p * 2][1], bf[p * 2 + 1][0], bf[p * 2 + 1][1],
                        b_addr[p] + ko);
#pragma unroll
            for (int mt = 0; mt < 4; mt++) {
#pragma unroll
                for (int ntile = 0; ntile < 8; ntile++) {
                    asm volatile(
                        "mma.sync.aligned.m16n8k16.row.col.f32.bf16.bf16.f32 "
                        "{%0,%1,%2,%3}, {%4,%5,%6,%7}, {%8,%9}, {%0,%1,%2,%3};\n"
                        : "+f"(acc[mt][ntile][0]), "+f"(acc[mt][ntile][1]),
                          "+f"(acc[mt][ntile][2]), "+f"(acc[mt][ntile][3])
                        : "r"(af[mt][0]), "r"(af[mt][1]), "r"(af[mt][2]), "r"(af[mt][3]),
                          "r"(bf[ntile][0]), "r"(bf[ntile][1]));
                }
            }
        }
        __syncthreads();
    }

    // ---- epilogue 1: store C tile (bf16, column-guarded for layer 3) ----
#pragma unroll
    for (int mt = 0; mt < 4; mt++) {
        int r0 = bm + wm + mt * 16 + gid;
#pragma unroll
        for (int ntile = 0; ntile < 8; ntile++) {
            int c = bn + wn + ntile * 8 + 2 * tg;
            if (c < N) {
                if (r0 < M) {
                    __nv_bfloat162 p =
                        __floats2bfloat162_rn(acc[mt][ntile][0], acc[mt][ntile][1]);
                    *(uint32_t*)&C[(size_t)r0 * N + c] = *(uint32_t*)&p;
                }
                if (r0 + 8 < M) {
                    __nv_bfloat162 p =
                        __floats2bfloat162_rn(acc[mt][ntile][2], acc[mt][ntile][3]);
                    *(uint32_t*)&C[(size_t)(r0 + 8) * N + c] = *(uint32_t*)&p;
                }
            }
        }
    }

    // ---- epilogue 2: fused attention dots (2 heads per CTA column) ----
    float* s_red = (float*)smem_h;                 // [128][2 heads][2]
    s_red[t] = 0.f;
    s_red[t + 256] = 0.f;
    __syncthreads();

    const int hbase  = blockIdx.x * 2;
    const int head_l = wn >> 7;                    // 0 or 1, whole warp
    const int hsafe  = (hbase + head_l < H) ? (hbase + head_l) : (H - 1);
    const bool hvalid = (hbase + head_l) < H;
    const float* asv = a_s + hsafe * 128;
    const float* adv = a_d + hsafe * 128;

    float csa[16], cda[16];
#pragma unroll
    for (int ntile = 0; ntile < 8; ntile++) {
        int cl = (wn & 127) + ntile * 8 + 2 * tg;
        csa[ntile * 2]     = asv[cl];
        csa[ntile * 2 + 1] = asv[cl + 1];
        cda[ntile * 2]     = adv[cl];
        cda[ntile * 2 + 1] = adv[cl + 1];
    }
#pragma unroll
    for (int mt = 0; mt < 4; mt++) {
#pragma unroll
        for (int half = 0; half < 2; half++) {
            float rs = 0.f, rd = 0.f;
#pragma unroll
            for (int ntile = 0; ntile < 8; ntile++) {
                rs = fmaf(acc[mt][ntile][half * 2],     csa[ntile * 2],     rs);
                rs = fmaf(acc[mt][ntile][half * 2 + 1], csa[ntile * 2 + 1], rs);
                rd = fmaf(acc[mt][ntile][half * 2],     cda[ntile * 2],     rd);
                rd = fmaf(acc[mt][ntile][half * 2 + 1], cda[ntile * 2 + 1], rd);
            }
            rs += __shfl_xor_sync(0xffffffffu, rs, 1);
            rs += __shfl_xor_sync(0xffffffffu, rs, 2);
            rd += __shfl_xor_sync(0xffffffffu, rd, 1);
            rd += __shfl_xor_sync(0xffffffffu, rd, 2);
            if (tg == 0 && hvalid) {
                int rl = wm + mt * 16 + half * 8 + gid;
                atomicAdd(&s_red[rl * 4 + head_l * 2],     rs);
                atomicAdd(&s_red[rl * 4 + head_l * 2 + 1], rd);
            }
        }
    }
    __syncthreads();
    {
        int rl = t >> 1, hl = t & 1;
        if (bm + rl < M && hbase + hl < H) {
            g_als[(bm + rl) * H + hbase + hl] = s_red[rl * 4 + hl * 2];
            g_ald[(bm + rl) * H + hbase + hl] = s_red[rl * 4 + hl * 2 + 1];
        }
    }
}

// ---------------- fused GAT softmax + aggregation, H=8 (R9 form) -----------
__global__ __launch_bounds__(256) void gat_fused8_k(
    const __nv_bfloat16* __restrict__ hw, const float* __restrict__ b,
    __nv_bfloat16* __restrict__ act)
{
    __shared__ float s_max[8], s_sum[8], s_ald[8];
    __shared__ float s_alpha[32][8];
    __shared__ int   s_srcs[32];

    const int d = blockIdx.x;
    const int t = threadIdx.x;
    const int beg = g_rowptr[d], deg = g_rowptr[d + 1] - beg;
    const int w = t >> 5, lane = t & 31;
    const int h = t & 7, j = t >> 3;

    if (t < 8) s_ald[t] = g_ald[d * 8 + t];

    {
        const float ald = g_ald[d * 8 + w];
        float m = -INFINITY;
        for (int i = lane; i < deg; i += 32) {
            int s = g_csrc[beg + i];
            float v = g_als[s * 8 + w] + ald;
            v = v > 0.f ? v : 0.2f * v;
            m = fmaxf(m, v);
        }
#pragma unroll
        for (int o = 16; o; o >>= 1)
            m = fmaxf(m, __shfl_xor_sync(0xffffffffu, m, o));
        float sum = 0.f;
        for (int i = lane; i < deg; i += 32) {
            int s = g_csrc[beg + i];
            float v = g_als[s * 8 + w] + ald;
            v = v > 0.f ? v : 0.2f * v;
            sum += __expf(v - m);
        }
#pragma unroll
        for (int o = 16; o; o >>= 1)
            sum += __shfl_xor_sync(0xffffffffu, sum, o);
        if (lane == 0) { s_max[w] = m; s_sum[w] = sum; }
    }
    __syncthreads();

    const int hh = t >> 5;
    const int ct = 4 * t;
    float4 a = make_float4(0.f, 0.f, 0.f, 0.f);
    for (int c0 = 0; c0 < deg; c0 += 32) {
        int cn = min(32, deg - c0);
        if (j < cn) {
            int s = g_csrc[beg + c0 + j];
            if (h == 0) s_srcs[j] = s;
            float v = g_als[s * 8 + h] + s_ald[h];
            v = v > 0.f ? v : 0.2f * v;
            s_alpha[j][h] = __expf(v - s_max[h]) / s_sum[h];
        }
        __syncthreads();
        for (int i = 0; i < cn; i++) {
            uint2 hv = *(const uint2*)(hw + (size_t)s_srcs[i] * 1024 + ct);
            float2 f0 = __bfloat1622float2(*(__nv_bfloat162*)&hv.x);
            float2 f1 = __bfloat1622float2(*(__nv_bfloat162*)&hv.y);
            const float al = s_alpha[i][hh];
            a.x = fmaf(f0.x, al, a.x);
            a.y = fmaf(f0.y, al, a.y);
            a.z = fmaf(f1.x, al, a.z);
            a.w = fmaf(f1.y, al, a.w);
        }
        __syncthreads();
    }

    const float4 bv = ((const float4*)b)[t];
    a.x = fmaxf(a.x + bv.x, 0.f);
    a.y = fmaxf(a.y + bv.y, 0.f);
    a.z = fmaxf(a.z + bv.z, 0.f);
    a.w = fmaxf(a.w + bv.w, 0.f);
    __nv_bfloat162 p0 = __floats2bfloat162_rn(a.x, a.y);
    __nv_bfloat162 p1 = __floats2bfloat162_rn(a.z, a.w);
    uint2 packed = make_uint2(*(uint32_t*)&p0, *(uint32_t*)&p1);
    *(uint2*)&act[(size_t)d * 1024 + ct] = packed;
}

// ---------------- fused GAT softmax + aggregation, H=1 (R9 form) -----------
__global__ __launch_bounds__(128) void gat_fused1_k(
    const __nv_bfloat16* __restrict__ hw, const float* __restrict__ b,
    float* __restrict__ out)
{
    __shared__ float red[128];
    __shared__ float s_alpha[32];
    __shared__ int   s_srcs[32];

    const int d = blockIdx.x;
    const int t = threadIdx.x;
    const int beg = g_rowptr[d], deg = g_rowptr[d + 1] - beg;
    const float ald = g_ald[d];

    float m = -INFINITY;
    for (int i = t; i < deg; i += 128) {
        float v = g_als[g_csrc[beg + i]] + ald;
        v = v > 0.f ? v : 0.2f * v;
        m = fmaxf(m, v);
    }
    red[t] = m; __syncthreads();
#pragma unroll
    for (int off = 64; off >= 1; off >>= 1) {
        if (t < off) red[t] = fmaxf(red[t], red[t + off]);
        __syncthreads();
    }
    const float mx = red[0];
    __syncthreads();

    float sum = 0.f;
    for (int i = t; i < deg; i += 128) {
        float v = g_als[g_csrc[beg + i]] + ald;
        v = v > 0.f ? v : 0.2f * v;
        sum += __expf(v - mx);
    }
    red[t] = sum; __syncthreads();
#pragma unroll
    for (int off = 64; off >= 1; off >>= 1) {
        if (t < off) red[t] += red[t + off];
        __syncthreads();
    }
    const float sm = red[0];
    __syncthreads();

    float acc = 0.f;
    for (int c0 = 0; c0 < deg; c0 += 32) {
        int cn = min(32, deg - c0);
        if (t < cn) {
            int s = g_csrc[beg + c0 + t];
            s_srcs[t] = s;
            float v = g_als[s] + ald;
            v = v > 0.f ? v : 0.2f * v;
            s_alpha[t] = __expf(v - mx) / sm;
        }
        __syncthreads();
        for (int i = 0; i < cn; i++)
            acc = fmaf(__bfloat162float(hw[(size_t)s_srcs[i] * 128 + t]),
                       s_alpha[i], acc);
        __syncthreads();
    }
    out[(size_t)d * 128 + t] = acc + b[t];
}

// ---------------- fused pair-MLP scorer ------------------------------------
__global__ __launch_bounds__(128) void mlp_k(
    const float* __restrict__ h3, const int* __restrict__ liq,
    const int* __restrict__ ing,
    const float* __restrict__ mw1, const float* __restrict__ mb1,
    const float* __restrict__ mw2, const float* __restrict__ mb2,
    const float* __restrict__ mw3, const float* __restrict__ mb3,
    float* __restrict__ outp)
{
    __shared__ float pair[256];
    __shared__ float z1[128];
    __shared__ float z2[64];
    int row = blockIdx.x, t = threadIdx.x;
    int L = liq[row], I = ing[row];
    pair[t]       = h3[(size_t)L * 128 + t];
    pair[128 + t] = h3[(size_t)I * 128 + t];
    __syncthreads();
    float acc = mb1[t];
#pragma unroll 8
    for (int i = 0; i < 256; i++) acc = fmaf(pair[i], mw1[i * 128 + t], acc);
    z1[t] = fmaxf(acc, 0.f);
    __syncthreads();
    if (t < 64) {
        float a2 = mb2[t];
#pragma unroll 8
        for (int i = 0; i < 128; i++) a2 = fmaf(z1[i], mw2[i * 64 + t], a2);
        z2[t] = fmaxf(a2, 0.f);
    }
    __syncthreads();
    if (t < 32) {
        float a3 = fmaf(z2[t], mw3[t], z2[t + 32] * mw3[t + 32]);
#pragma unroll
        for (int o = 16; o; o >>= 1) a3 += __shfl_down_sync(0xffffffffu, a3, o);
        if (t == 0) outp[row] = 1.f / (1.f + expf(-(a3 + mb3[0])));
    }
}

extern "C" void kernel_launch(void* const* d_in, const int* in_sizes, int n_in,
                              void* d_out, int out_size)
{
    const float* x   = (const float*)d_in[0];
    const int*   ei  = (const int*)d_in[1];
    const int*   liq = (const int*)d_in[2];
    const int*   ing = (const int*)d_in[3];
    const float* W1  = (const float*)d_in[4];
    const float* as1 = (const float*)d_in[5];
    const float* ad1 = (const float*)d_in[6];
    const float* b1  = (const float*)d_in[7];
    const float* W2  = (const float*)d_in[8];
    const float* as2 = (const float*)d_in[9];
    const float* ad2 = (const float*)d_in[10];
    const float* b2  = (const float*)d_in[11];
    const float* W3  = (const float*)d_in[12];
    const float* as3 = (const float*)d_in[13];
    const float* ad3 = (const float*)d_in[14];
    const float* b3  = (const float*)d_in[15];
    const float* mw1 = (const float*)d_in[16];
    const float* mb1 = (const float*)d_in[17];
    const float* mw2 = (const float*)d_in[18];
    const float* mb2 = (const float*)d_in[19];
    const float* mw3 = (const float*)d_in[20];
    const float* mb3 = (const float*)d_in[21];
    float* outp = (float*)d_out;

    cudaFuncSetAttribute(mma_gemm_k,
                         cudaFuncAttributeMaxDynamicSharedMemorySize,
                         GEMM_SMEM_BYTES);

    float* bufC;
    __nv_bfloat16 *hw, *act, *xb, *wt1, *wt2, *wt3;
    cudaGetSymbolAddress((void**)&hw,   g_hw);
    cudaGetSymbolAddress((void**)&bufC, g_bufC);
    cudaGetSymbolAddress((void**)&act,  g_act);
    cudaGetSymbolAddress((void**)&xb,   g_xb);
    cudaGetSymbolAddress((void**)&wt1,  g_wt1);
    cudaGetSymbolAddress((void**)&wt2,  g_wt2);
    cudaGetSymbolAddress((void**)&wt3,  g_wt3);

    cvt_all_k<<<(SEG4 + 255) / 256, 256>>>(x, W1, W2, W3);

    build_hist_k<<<(E_TOT + 255) / 256, 256>>>(ei);
    scan_all_k<<<NBLK, 1024>>>();
    scatter_k<<<(E_TOT + 255) / 256, 256>>>();

    const int gy = (N_NODES + 127) / 128;   // 196
    dim3 grid8(4, gy);                       // 1024 cols / 256
    dim3 grid1(1, gy);                       // 128 cols (padded Bt)

    mma_gemm_k<<<grid8, 256, GEMM_SMEM_BYTES>>>(xb, wt1, hw, N_NODES, 1024, 64,
                                                as1, ad1, 8);
    gat_fused8_k<<<N_NODES, 256>>>(hw, b1, act);

    mma_gemm_k<<<grid8, 256, GEMM_SMEM_BYTES>>>(act, wt2, hw, N_NODES, 1024, 1024,
                                                as2, ad2, 8);
    gat_fused8_k<<<N_NODES, 256>>>(hw, b2, act);

    mma_gemm_k<<<grid1, 256, GEMM_SMEM_BYTES>>>(act, wt3, hw, N_NODES, 128, 1024,
                                                as3, ad3, 1);
    gat_fused1_k<<<N_NODES, 128>>>(hw, b3, bufC);

    mlp_k<<<4096, 128>>>(bufC, liq, ing, mw1, mb1, mw2, mb2, mw3, mb3, outp);
}

// round 12
// speedup vs baseline: 1.0397x; 1.0397x over previous
#include <cuda_runtime.h>
#include <cuda_bf16.h>
#include <math.h>
#include <stdint.h>

#define N_NODES 25000
#define N_EDGES 200000
#define E_TOT   (N_EDGES + N_NODES)
#define C_HID   128
#define F_BIG   1024
#define NBLK    ((N_NODES + 1023) / 1024)   // 25

// ---------------- device scratch -------------------------------------------
__device__ __nv_bfloat16  g_hw  [N_NODES * F_BIG];
__device__ __nv_bfloat16  g_act [N_NODES * F_BIG];
__device__ __nv_bfloat16  g_xb  [N_NODES * 64];
__device__ __nv_bfloat16  g_wt1 [1024 * 64];
__device__ __nv_bfloat16  g_wt2 [1024 * 1024];
__device__ __nv_bfloat16  g_wt3 [256 * 1024];    // padded to 256 rows (zeros)
__device__ float          g_bufC[N_NODES * C_HID];
__device__ float g_als [N_NODES * 8];
__device__ float g_ald [N_NODES * 8];
__device__ int   g_src [E_TOT];
__device__ int   g_dst [E_TOT];
__device__ int   g_rowptr[N_NODES + 1];
__device__ int   g_wptr  [N_NODES];
__device__ int   g_csrc  [E_TOT];
__device__ int   g_bsum  [NBLK];
__device__ int   g_sync;

// ---------------- cp.async helpers -----------------------------------------
__device__ __forceinline__ void cpa16(void* sdst, const void* gsrc, int sz) {
    uint32_t sa = (uint32_t)__cvta_generic_to_shared(sdst);
    asm volatile("cp.async.cg.shared.global [%0], [%1], 16, %2;"
                 :: "r"(sa), "l"(gsrc), "r"(sz) : "memory");
}
__device__ __forceinline__ void cpa_commit() {
    asm volatile("cp.async.commit_group;" ::: "memory");
}
template <int W> __device__ __forceinline__ void cpa_wait() {
    asm volatile("cp.async.wait_group %0;" :: "n"(W) : "memory");
}
__device__ __forceinline__ void ldsm_x4(uint32_t& r0, uint32_t& r1,
                                        uint32_t& r2, uint32_t& r3, uint32_t a) {
    asm volatile("ldmatrix.sync.aligned.m8n8.x4.shared.b16 {%0,%1,%2,%3}, [%4];"
                 : "=r"(r0), "=r"(r1), "=r"(r2), "=r"(r3) : "r"(a));
}

// ---------------- fused conversions (+ wptr zeroing, + wt3 pad) -------------
#define SEG0 (N_NODES * 64)
#define SEG1 (SEG0 + 64 * 1024)
#define SEG2 (SEG1 + 1024 * 1024)
#define SEG3 (SEG2 + 1024 * 128)
#define SEG4 (SEG3 + 128 * 1024)
__global__ void cvt_all_k(const float* __restrict__ x,
                          const float* __restrict__ W1,
                          const float* __restrict__ W2,
                          const float* __restrict__ W3) {
    int i = blockIdx.x * blockDim.x + threadIdx.x;
    if (i < N_NODES) g_wptr[i] = 0;
    if (i < SEG0) {
        g_xb[i] = __float2bfloat16(x[i]);
    } else if (i < SEG1) {
        int j = i - SEG0;  int k = j >> 10, n = j & 1023;
        g_wt1[(size_t)n * 64 + k] = __float2bfloat16(W1[j]);
    } else if (i < SEG2) {
        int j = i - SEG1;  int k = j >> 10, n = j & 1023;
        g_wt2[(size_t)n * 1024 + k] = __float2bfloat16(W2[j]);
    } else if (i < SEG3) {
        int j = i - SEG2;  int k = j >> 7, n = j & 127;
        g_wt3[(size_t)n * 1024 + k] = __float2bfloat16(W3[j]);
    } else if (i < SEG4) {
        int j = i - SEG3;
        g_wt3[(size_t)(128 + (j >> 10)) * 1024 + (j & 1023)] = __float2bfloat16(0.f);
    }
}

// ---------------- edge build + histogram (fused) ----------------------------
__global__ void build_hist_k(const int* __restrict__ ei) {
    int i = blockIdx.x * blockDim.x + threadIdx.x;
    if (i == 0) g_sync = 0;
    if (i < N_EDGES) {
        int s = ei[i], d = ei[N_EDGES + i];
        g_src[i] = s;
        g_dst[i] = d;
        atomicAdd(&g_wptr[d], 1);
    } else if (i < E_TOT) {
        int n = i - N_EDGES;
        g_src[i] = n;
        g_dst[i] = n;
        atomicAdd(&g_wptr[n], 1);
    }
}

// ---------------- single-kernel 3-phase scan --------------------------------
__global__ __launch_bounds__(1024) void scan_all_k() {
    __shared__ int ws[32];
    __shared__ int s_off;
    int t = threadIdx.x, lane = t & 31, wid = t >> 5;
    int idx = blockIdx.x * 1024 + t;
    int v = (idx < N_NODES) ? g_wptr[idx] : 0;
    int incl = v;
#pragma unroll
    for (int off = 1; off < 32; off <<= 1) {
        int y = __shfl_up_sync(0xffffffffu, incl, off);
        if (lane >= off) incl += y;
    }
    if (lane == 31) ws[wid] = incl;
    __syncthreads();
    if (wid == 0) {
        int s = ws[lane], si = s;
#pragma unroll
        for (int off = 1; off < 32; off <<= 1) {
            int y = __shfl_up_sync(0xffffffffu, si, off);
            if (lane >= off) si += y;
        }
        ws[lane] = si - s;
    }
    __syncthreads();
    int excl = incl - v + ws[wid];
    if (t == 1023) g_bsum[blockIdx.x] = excl + v;
    __threadfence();
    __syncthreads();
    if (t == 0) {
        atomicAdd(&g_sync, 1);
        while (atomicAdd(&g_sync, 0) < NBLK) {}
    }
    __syncthreads();
    if (t < 32) {
        int v2 = (lane < NBLK) ? g_bsum[lane] : 0;
        int i2 = v2;
#pragma unroll
        for (int off = 1; off < 32; off <<= 1) {
            int y = __shfl_up_sync(0xffffffffu, i2, off);
            if (lane >= off) i2 += y;
        }
        if (lane == (int)blockIdx.x) s_off = i2 - v2;
    }
    __syncthreads();
    int val = excl + s_off;
    if (idx < N_NODES) {
        g_rowptr[idx] = val;
        g_wptr[idx]   = val;
    }
    if (idx == 0) g_rowptr[N_NODES] = E_TOT;
}
__global__ void scatter_k() {
    int e = blockIdx.x * blockDim.x + threadIdx.x;
    if (e < E_TOT) {
        int pos = atomicAdd(&g_wptr[g_dst[e]], 1);
        g_csrc[pos] = g_src[e];
    }
}

// ---------------- bf16 tensor-core GEMM, CTA 128x256, 512 thr, att-dots ----
// C[M,N] = A[M,K] @ Bt[Npad,K]^T. 16 warps, warp tile 64x32 (acc 64 regs).
// BK=32, 3 cp.async stages. CTA column spans 2 heads (BN=256).
#define GSTAGES 3
#define T_STRIDE 40
#define ROWS_AB  384                              // 128 A rows + 256 B rows
#define STAGE_ELEMS (ROWS_AB * T_STRIDE)          // 15360
#define STAGE_BYTES (STAGE_ELEMS * 2)             // 30720
#define GEMM_SMEM_BYTES (GSTAGES * STAGE_BYTES)   // 92160

__global__ __launch_bounds__(512, 1) void mma_gemm_k(
    const __nv_bfloat16* __restrict__ A, const __nv_bfloat16* __restrict__ Bt,
    __nv_bfloat16* __restrict__ C, int M, int N, int K,
    const float* __restrict__ a_s, const float* __restrict__ a_d, int H)
{
    extern __shared__ __align__(16) __nv_bfloat16 smem_h[];

    const int t    = threadIdx.x;
    const int bm   = blockIdx.y * 128;
    const int bn   = blockIdx.x * 256;
    const int warp = t >> 5, lane = t & 31;
    const int wm   = (warp >> 3) * 64;       // 0 or 64
    const int wn   = (warp & 7) * 32;        // 0..224
    const int gid  = lane >> 2;
    const int tg   = lane & 3;

    const int kTiles = K >> 5;

    auto issue_tile = [&](int kt, int st) {
        __nv_bfloat16* base = smem_h + st * STAGE_ELEMS;
#pragma unroll
        for (int qc = 0; qc < 3; qc++) {
            int c = t + qc * 512;              // 0..1535
            int row = c >> 2, ce = (c & 3) * 8;
            if (row < 128) {
                int grow = bm + row;
                int sz = (grow < M) ? 16 : 0;
                if (grow >= M) grow = M - 1;
                cpa16(&base[row * T_STRIDE + ce],
                      A + (size_t)grow * K + kt * 32 + ce, sz);
            } else {
                int rb = row - 128;
                cpa16(&base[row * T_STRIDE + ce],
                      Bt + (size_t)(bn + rb) * K + kt * 32 + ce, 16);
            }
        }
    };

    // ldmatrix lane addresses (stage 0, k-step 0)
    const int q = lane >> 3, r = lane & 7;
    const uint32_t s0 = (uint32_t)__cvta_generic_to_shared(smem_h);
    uint32_t a_addr[4], b_addr[2];
#pragma unroll
    for (int mt = 0; mt < 4; mt++) {
        int row = wm + mt * 16 + r + ((q & 1) << 3);
        int col = (q >> 1) << 3;
        a_addr[mt] = s0 + (row * T_STRIDE + col) * 2;
    }
#pragma unroll
    for (int p = 0; p < 2; p++) {
        int row = 128 + wn + ((p * 2 + (q >> 1)) << 3) + r;
        int col = (q & 1) << 3;
        b_addr[p] = s0 + (row * T_STRIDE + col) * 2;
    }

    float acc[4][4][4];
#pragma unroll
    for (int i = 0; i < 4; i++)
#pragma unroll
        for (int j = 0; j < 4; j++)
#pragma unroll
            for (int z = 0; z < 4; z++) acc[i][j][z] = 0.f;

#pragma unroll
    for (int s = 0; s < GSTAGES - 1; s++) {
        if (s < kTiles) issue_tile(s, s);
        cpa_commit();
    }

    for (int kt = 0; kt < kTiles; kt++) {
        cpa_wait<GSTAGES - 2>();
        __syncthreads();

        int nt = kt + GSTAGES - 1;
        if (nt < kTiles) issue_tile(nt, nt % GSTAGES);
        cpa_commit();

        const uint32_t soff = (uint32_t)((kt % GSTAGES) * STAGE_BYTES);

#pragma unroll
        for (int ks = 0; ks < 2; ks++) {
            const uint32_t ko = soff + ks * 32;
            uint32_t af[4][4], bf[4][2];
#pragma unroll
            for (int mt = 0; mt < 4; mt++)
                ldsm_x4(af[mt][0], af[mt][1], af[mt][2], af[mt][3], a_addr[mt] + ko);
#pragma unroll
            for (int p = 0; p < 2; p++)
                ldsm_x4(bf[p * 2][0], bf[p * 2][1], bf[p * 2 + 1][0], bf[p * 2 + 1][1],
                        b_addr[p] + ko);
#pragma unroll
            for (int mt = 0; mt < 4; mt++) {
#pragma unroll
                for (int ntile = 0; ntile < 4; ntile++) {
                    asm volatile(
                        "mma.sync.aligned.m16n8k16.row.col.f32.bf16.bf16.f32 "
                        "{%0,%1,%2,%3}, {%4,%5,%6,%7}, {%8,%9}, {%0,%1,%2,%3};\n"
                        : "+f"(acc[mt][ntile][0]), "+f"(acc[mt][ntile][1]),
                          "+f"(acc[mt][ntile][2]), "+f"(acc[mt][ntile][3])
                        : "r"(af[mt][0]), "r"(af[mt][1]), "r"(af[mt][2]), "r"(af[mt][3]),
                          "r"(bf[ntile][0]), "r"(bf[ntile][1]));
                }
            }
        }
        __syncthreads();
    }

    // ---- epilogue 1: store C tile (bf16, column-guarded for layer 3) ----
#pragma unroll
    for (int mt = 0; mt < 4; mt++) {
        int r0 = bm + wm + mt * 16 + gid;
#pragma unroll
        for (int ntile = 0; ntile < 4; ntile++) {
            int c = bn + wn + ntile * 8 + 2 * tg;
            if (c < N) {
                if (r0 < M) {
                    __nv_bfloat162 p =
                        __floats2bfloat162_rn(acc[mt][ntile][0], acc[mt][ntile][1]);
                    *(uint32_t*)&C[(size_t)r0 * N + c] = *(uint32_t*)&p;
                }
                if (r0 + 8 < M) {
                    __nv_bfloat162 p =
                        __floats2bfloat162_rn(acc[mt][ntile][2], acc[mt][ntile][3]);
                    *(uint32_t*)&C[(size_t)(r0 + 8) * N + c] = *(uint32_t*)&p;
                }
            }
        }
    }

    // ---- epilogue 2: fused attention dots (2 heads per CTA column) ----
    float* s_red = (float*)smem_h;                 // [128][2 heads][2]
    s_red[t] = 0.f;
    __syncthreads();

    const int hbase  = blockIdx.x * 2;
    const int head_l = wn >> 7;                    // 0 or 1, whole warp
    const int hsafe  = (hbase + head_l < H) ? (hbase + head_l) : (H - 1);
    const bool hvalid = (hbase + head_l) < H;
    const float* asv = a_s + hsafe * 128;
    const float* adv = a_d + hsafe * 128;

    float csa[8], cda[8];
#pragma unroll
    for (int ntile = 0; ntile < 4; ntile++) {
        int cl = (wn & 127) + ntile * 8 + 2 * tg;
        csa[ntile * 2]     = asv[cl];
        csa[ntile * 2 + 1] = asv[cl + 1];
        cda[ntile * 2]     = adv[cl];
        cda[ntile * 2 + 1] = adv[cl + 1];
    }
#pragma unroll
    for (int mt = 0; mt < 4; mt++) {
#pragma unroll
        for (int half = 0; half < 2; half++) {
            float rs = 0.f, rd = 0.f;
#pragma unroll
            for (int ntile = 0; ntile < 4; ntile++) {
                rs = fmaf(acc[mt][ntile][half * 2],     csa[ntile * 2],     rs);
                rs = fmaf(acc[mt][ntile][half * 2 + 1], csa[ntile * 2 + 1], rs);
                rd = fmaf(acc[mt][ntile][half * 2],     cda[ntile * 2],     rd);
                rd = fmaf(acc[mt][ntile][half * 2 + 1], cda[ntile * 2 + 1], rd);
            }
            rs += __shfl_xor_sync(0xffffffffu, rs, 1);
            rs += __shfl_xor_sync(0xffffffffu, rs, 2);
            rd += __shfl_xor_sync(0xffffffffu, rd, 1);
            rd += __shfl_xor_sync(0xffffffffu, rd, 2);
            if (tg == 0 && hvalid) {
                int rl = wm + mt * 16 + half * 8 + gid;
                atomicAdd(&s_red[rl * 4 + head_l * 2],     rs);
                atomicAdd(&s_red[rl * 4 + head_l * 2 + 1], rd);
            }
        }
    }
    __syncthreads();
    if (t < 256) {
        int rl = t >> 1, hl = t & 1;
        if (bm + rl < M && hbase + hl < H) {
            g_als[(bm + rl) * H + hbase + hl] = s_red[rl * 4 + hl * 2];
            g_ald[(bm + rl) * H + hbase + hl] = s_red[rl * 4 + hl * 2 + 1];
        }
    }
}

// ---------------- fused GAT softmax + aggregation, H=8 (R9 form) -----------
__global__ __launch_bounds__(256) void gat_fused8_k(
    const __nv_bfloat16* __restrict__ hw, const float* __restrict__ b,
    __nv_bfloat16* __restrict__ act)
{
    __shared__ float s_max[8], s_sum[8], s_ald[8];
    __shared__ float s_alpha[32][8];
    __shared__ int   s_srcs[32];

    const int d = blockIdx.x;
    const int t = threadIdx.x;
    const int beg = g_rowptr[d], deg = g_rowptr[d + 1] - beg;
    const int w = t >> 5, lane = t & 31;
    const int h = t & 7, j = t >> 3;

    if (t < 8) s_ald[t] = g_ald[d * 8 + t];

    {
        const float ald = g_ald[d * 8 + w];
        float m = -INFINITY;
        for (int i = lane; i < deg; i += 32) {
            int s = g_csrc[beg + i];
            float v = g_als[s * 8 + w] + ald;
            v = v > 0.f ? v : 0.2f * v;
            m = fmaxf(m, v);
        }
#pragma unroll
        for (int o = 16; o; o >>= 1)
            m = fmaxf(m, __shfl_xor_sync(0xffffffffu, m, o));
        float sum = 0.f;
        for (int i = lane; i < deg; i += 32) {
            int s = g_csrc[beg + i];
            float v = g_als[s * 8 + w] + ald;
            v = v > 0.f ? v : 0.2f * v;
            sum += __expf(v - m);
        }
#pragma unroll
        for (int o = 16; o; o >>= 1)
            sum += __shfl_xor_sync(0xffffffffu, sum, o);
        if (lane == 0) { s_max[w] = m; s_sum[w] = sum; }
    }
    __syncthreads();

    const int hh = t >> 5;
    const int ct = 4 * t;
    float4 a = make_float4(0.f, 0.f, 0.f, 0.f);
    for (int c0 = 0; c0 < deg; c0 += 32) {
        int cn = min(32, deg - c0);
        if (j < cn) {
            int s = g_csrc[beg + c0 + j];
            if (h == 0) s_srcs[j] = s;
            float v = g_als[s * 8 + h] + s_ald[h];
            v = v > 0.f ? v : 0.2f * v;
            s_alpha[j][h] = __expf(v - s_max[h]) / s_sum[h];
        }
        __syncthreads();
        for (int i = 0; i < cn; i++) {
            uint2 hv = *(const uint2*)(hw + (size_t)s_srcs[i] * 1024 + ct);
            float2 f0 = __bfloat1622float2(*(__nv_bfloat162*)&hv.x);
            float2 f1 = __bfloat1622float2(*(__nv_bfloat162*)&hv.y);
            const float al = s_alpha[i][hh];
            a.x = fmaf(f0.x, al, a.x);
            a.y = fmaf(f0.y, al, a.y);
            a.z = fmaf(f1.x, al, a.z);
            a.w = fmaf(f1.y, al, a.w);
        }
        __syncthreads();
    }

    const float4 bv = ((const float4*)b)[t];
    a.x = fmaxf(a.x + bv.x, 0.f);
    a.y = fmaxf(a.y + bv.y, 0.f);
    a.z = fmaxf(a.z + bv.z, 0.f);
    a.w = fmaxf(a.w + bv.w, 0.f);
    __nv_bfloat162 p0 = __floats2bfloat162_rn(a.x, a.y);
    __nv_bfloat162 p1 = __floats2bfloat162_rn(a.z, a.w);
    uint2 packed = make_uint2(*(uint32_t*)&p0, *(uint32_t*)&p1);
    *(uint2*)&act[(size_t)d * 1024 + ct] = packed;
}

// ---------------- fused GAT softmax + aggregation, H=1 (R9 form) -----------
__global__ __launch_bounds__(128) void gat_fused1_k(
    const __nv_bfloat16* __restrict__ hw, const float* __restrict__ b,
    float* __restrict__ out)
{
    __shared__ float red[128];
    __shared__ float s_alpha[32];
    __shared__ int   s_srcs[32];

    const int d = blockIdx.x;
    const int t = threadIdx.x;
    const int beg = g_rowptr[d], deg = g_rowptr[d + 1] - beg;
    const float ald = g_ald[d];

    float m = -INFINITY;
    for (int i = t; i < deg; i += 128) {
        float v = g_als[g_csrc[beg + i]] + ald;
        v = v > 0.f ? v : 0.2f * v;
        m = fmaxf(m, v);
    }
    red[t] = m; __syncthreads();
#pragma unroll
    for (int off = 64; off >= 1; off >>= 1) {
        if (t < off) red[t] = fmaxf(red[t], red[t + off]);
        __syncthreads();
    }
    const float mx = red[0];
    __syncthreads();

    float sum = 0.f;
    for (int i = t; i < deg; i += 128) {
        float v = g_als[g_csrc[beg + i]] + ald;
        v = v > 0.f ? v : 0.2f * v;
        sum += __expf(v - mx);
    }
    red[t] = sum; __syncthreads();
#pragma unroll
    for (int off = 64; off >= 1; off >>= 1) {
        if (t < off) red[t] += red[t + off];
        __syncthreads();
    }
    const float sm = red[0];
    __syncthreads();

    float acc = 0.f;
    for (int c0 = 0; c0 < deg; c0 += 32) {
        int cn = min(32, deg - c0);
        if (t < cn) {
            int s = g_csrc[beg + c0 + t];
            s_srcs[t] = s;
            float v = g_als[s] + ald;
            v = v > 0.f ? v : 0.2f * v;
            s_alpha[t] = __expf(v - mx) / sm;
        }
        __syncthreads();
        for (int i = 0; i < cn; i++)
            acc = fmaf(__bfloat162float(hw[(size_t)s_srcs[i] * 128 + t]),
                       s_alpha[i], acc);
        __syncthreads();
    }
    out[(size_t)d * 128 + t] = acc + b[t];
}

// ---------------- fused pair-MLP scorer ------------------------------------
__global__ __launch_bounds__(128) void mlp_k(
    const float* __restrict__ h3, const int* __restrict__ liq,
    const int* __restrict__ ing,
    const float* __restrict__ mw1, const float* __restrict__ mb1,
    const float* __restrict__ mw2, const float* __restrict__ mb2,
    const float* __restrict__ mw3, const float* __restrict__ mb3,
    float* __restrict__ outp)
{
    __shared__ float pair[256];
    __shared__ float z1[128];
    __shared__ float z2[64];
    int row = blockIdx.x, t = threadIdx.x;
    int L = liq[row], I = ing[row];
    pair[t]       = h3[(size_t)L * 128 + t];
    pair[128 + t] = h3[(size_t)I * 128 + t];
    __syncthreads();
    float acc = mb1[t];
#pragma unroll 8
    for (int i = 0; i < 256; i++) acc = fmaf(pair[i], mw1[i * 128 + t], acc);
    z1[t] = fmaxf(acc, 0.f);
    __syncthreads();
    if (t < 64) {
        float a2 = mb2[t];
#pragma unroll 8
        for (int i = 0; i < 128; i++) a2 = fmaf(z1[i], mw2[i * 64 + t], a2);
        z2[t] = fmaxf(a2, 0.f);
    }
    __syncthreads();
    if (t < 32) {
        float a3 = fmaf(z2[t], mw3[t], z2[t + 32] * mw3[t + 32]);
#pragma unroll
        for (int o = 16; o; o >>= 1) a3 += __shfl_down_sync(0xffffffffu, a3, o);
        if (t == 0) outp[row] = 1.f / (1.f + expf(-(a3 + mb3[0])));
    }
}

extern "C" void kernel_launch(void* const* d_in, const int* in_sizes, int n_in,
                              void* d_out, int out_size)
{
    const float* x   = (const float*)d_in[0];
    const int*   ei  = (const int*)d_in[1];
    const int*   liq = (const int*)d_in[2];
    const int*   ing = (const int*)d_in[3];
    const float* W1  = (const float*)d_in[4];
    const float* as1 = (const float*)d_in[5];
    const float* ad1 = (const float*)d_in[6];
    const float* b1  = (const float*)d_in[7];
    const float* W2  = (const float*)d_in[8];
    const float* as2 = (const float*)d_in[9];
    const float* ad2 = (const float*)d_in[10];
    const float* b2  = (const float*)d_in[11];
    const float* W3  = (const float*)d_in[12];
    const float* as3 = (const float*)d_in[13];
    const float* ad3 = (const float*)d_in[14];
    const float* b3  = (const float*)d_in[15];
    const float* mw1 = (const float*)d_in[16];
    const float* mb1 = (const float*)d_in[17];
    const float* mw2 = (const float*)d_in[18];
    const float* mb2 = (const float*)d_in[19];
    const float* mw3 = (const float*)d_in[20];
    const float* mb3 = (const float*)d_in[21];
    float* outp = (float*)d_out;

    cudaFuncSetAttribute(mma_gemm_k,
                         cudaFuncAttributeMaxDynamicSharedMemorySize,
                         GEMM_SMEM_BYTES);

    float* bufC;
    __nv_bfloat16 *hw, *act, *xb, *wt1, *wt2, *wt3;
    cudaGetSymbolAddress((void**)&hw,   g_hw);
    cudaGetSymbolAddress((void**)&bufC, g_bufC);
    cudaGetSymbolAddress((void**)&act,  g_act);
    cudaGetSymbolAddress((void**)&xb,   g_xb);
    cudaGetSymbolAddress((void**)&wt1,  g_wt1);
    cudaGetSymbolAddress((void**)&wt2,  g_wt2);
    cudaGetSymbolAddress((void**)&wt3,  g_wt3);

    cvt_all_k<<<(SEG4 + 255) / 256, 256>>>(x, W1, W2, W3);

    build_hist_k<<<(E_TOT + 255) / 256, 256>>>(ei);
    scan_all_k<<<NBLK, 1024>>>();
    scatter_k<<<(E_TOT + 255) / 256, 256>>>();

    const int gy = (N_NODES + 127) / 128;   // 196
    dim3 grid8(4, gy);                       // 1024 cols / 256
    dim3 grid1(1, gy);                       // 128 cols (padded Bt)

    mma_gemm_k<<<grid8, 512, GEMM_SMEM_BYTES>>>(xb, wt1, hw, N_NODES, 1024, 64,
                                                as1, ad1, 8);
    gat_fused8_k<<<N_NODES, 256>>>(hw, b1, act);

    mma_gemm_k<<<grid8, 512, GEMM_SMEM_BYTES>>>(act, wt2, hw, N_NODES, 1024, 1024,
                                                as2, ad2, 8);
    gat_fused8_k<<<N_NODES, 256>>>(hw, b2, act);

    mma_gemm_k<<<grid1, 512, GEMM_SMEM_BYTES>>>(act, wt3, hw, N_NODES, 128, 1024,
                                                as3, ad3, 1);
    gat_fused1_k<<<N_NODES, 128>>>(hw, b3, bufC);

    mlp_k<<<4096, 128>>>(bufC, liq, ing, mw1, mb1, mw2, mb2, mw3, mb3, outp);
}

// round 13
// speedup vs baseline: 1.1324x; 1.0891x over previous
#include <cuda_runtime.h>
#include <cuda_bf16.h>
#include <math.h>
#include <stdint.h>

#define N_NODES 25000
#define N_EDGES 200000
#define E_TOT   (N_EDGES + N_NODES)
#define C_HID   128
#define F_BIG   1024
#define NBLK    ((N_NODES + 1023) / 1024)   // 25

// ---------------- device scratch -------------------------------------------
__device__ __nv_bfloat16  g_hw  [N_NODES * F_BIG];
__device__ __nv_bfloat16  g_act [N_NODES * F_BIG];
__device__ __nv_bfloat16  g_xb  [N_NODES * 64];
__device__ __nv_bfloat16  g_wt1 [1024 * 64];
__device__ __nv_bfloat16  g_wt2 [1024 * 1024];
__device__ __nv_bfloat16  g_wt3 [128 * 1024];
__device__ float          g_bufC[N_NODES * C_HID];
__device__ float g_als [N_NODES * 8];
__device__ float g_ald [N_NODES * 8];
__device__ int   g_src [E_TOT];
__device__ int   g_dst [E_TOT];
__device__ int   g_rowptr[N_NODES + 1];
__device__ int   g_wptr  [N_NODES];
__device__ int   g_csrc  [E_TOT];
__device__ int   g_bsum  [NBLK];

// ---------------- cp.async helpers -----------------------------------------
__device__ __forceinline__ void cpa16(void* sdst, const void* gsrc, int sz) {
    uint32_t sa = (uint32_t)__cvta_generic_to_shared(sdst);
    asm volatile("cp.async.cg.shared.global [%0], [%1], 16, %2;"
                 :: "r"(sa), "l"(gsrc), "r"(sz) : "memory");
}
__device__ __forceinline__ void cpa_commit() {
    asm volatile("cp.async.commit_group;" ::: "memory");
}
template <int W> __device__ __forceinline__ void cpa_wait() {
    asm volatile("cp.async.wait_group %0;" :: "n"(W) : "memory");
}
__device__ __forceinline__ void ldsm_x4(uint32_t& r0, uint32_t& r1,
                                        uint32_t& r2, uint32_t& r3, uint32_t a) {
    asm volatile("ldmatrix.sync.aligned.m8n8.x4.shared.b16 {%0,%1,%2,%3}, [%4];"
                 : "=r"(r0), "=r"(r1), "=r"(r2), "=r"(r3) : "r"(a));
}

// ---------------- conversions (split for stream overlap) --------------------
#define SEGX (N_NODES * 64)
#define SEGXW1 (SEGX + 64 * 1024)
__global__ void cvt_xw1_k(const float* __restrict__ x,
                          const float* __restrict__ W1) {
    int i = blockIdx.x * blockDim.x + threadIdx.x;
    if (i < SEGX) {
        g_xb[i] = __float2bfloat16(x[i]);
    } else if (i < SEGXW1) {
        int j = i - SEGX;  int k = j >> 10, n = j & 1023;
        g_wt1[(size_t)n * 64 + k] = __float2bfloat16(W1[j]);
    }
}
#define SEGW2 (1024 * 1024)
#define SEGW23 (SEGW2 + 1024 * 128)
__global__ void cvt_w23_k(const float* __restrict__ W2,
                          const float* __restrict__ W3) {
    int i = blockIdx.x * blockDim.x + threadIdx.x;
    if (i < SEGW2) {
        int k = i >> 10, n = i & 1023;
        g_wt2[(size_t)n * 1024 + k] = __float2bfloat16(W2[i]);
    } else if (i < SEGW23) {
        int j = i - SEGW2;  int k = j >> 7, n = j & 127;
        g_wt3[(size_t)n * 1024 + k] = __float2bfloat16(W3[j]);
    }
}

// ---------------- CSR chain -------------------------------------------------
__global__ void zero_k() {
    int i = blockIdx.x * blockDim.x + threadIdx.x;
    if (i < N_NODES) g_wptr[i] = 0;
}
__global__ void build_hist_k(const int* __restrict__ ei) {
    int i = blockIdx.x * blockDim.x + threadIdx.x;
    if (i < N_EDGES) {
        int s = ei[i], d = ei[N_EDGES + i];
        g_src[i] = s;
        g_dst[i] = d;
        atomicAdd(&g_wptr[d], 1);
    } else if (i < E_TOT) {
        int n = i - N_EDGES;
        g_src[i] = n;
        g_dst[i] = n;
        atomicAdd(&g_wptr[n], 1);
    }
}
__global__ __launch_bounds__(1024) void scan1_k() {
    __shared__ int ws[32];
    int t = threadIdx.x, lane = t & 31, wid = t >> 5;
    int idx = blockIdx.x * 1024 + t;
    int v = (idx < N_NODES) ? g_wptr[idx] : 0;
    int incl = v;
#pragma unroll
    for (int off = 1; off < 32; off <<= 1) {
        int y = __shfl_up_sync(0xffffffffu, incl, off);
        if (lane >= off) incl += y;
    }
    if (lane == 31) ws[wid] = incl;
    __syncthreads();
    if (wid == 0) {
        int s = ws[lane], si = s;
#pragma unroll
        for (int off = 1; off < 32; off <<= 1) {
            int y = __shfl_up_sync(0xffffffffu, si, off);
            if (lane >= off) si += y;
        }
        ws[lane] = si - s;
    }
    __syncthreads();
    int excl = incl - v + ws[wid];
    if (idx < N_NODES) g_rowptr[idx] = excl;
    if (t == 1023) g_bsum[blockIdx.x] = excl + v;
}
__global__ void scan2_k() {
    int lane = threadIdx.x;
    int v = (lane < NBLK) ? g_bsum[lane] : 0;
    int incl = v;
#pragma unroll
    for (int off = 1; off < 32; off <<= 1) {
        int y = __shfl_up_sync(0xffffffffu, incl, off);
        if (lane >= off) incl += y;
    }
    if (lane < NBLK) g_bsum[lane] = incl - v;
}
__global__ void scan3_k() {
    int idx = blockIdx.x * 1024 + threadIdx.x;
    if (idx < N_NODES) {
        int val = g_rowptr[idx] + g_bsum[blockIdx.x];
        g_rowptr[idx] = val;
        g_wptr[idx]   = val;
    }
    if (idx == 0) g_rowptr[N_NODES] = E_TOT;
}
__global__ void scatter_k() {
    int e = blockIdx.x * blockDim.x + threadIdx.x;
    if (e < E_TOT) {
        int pos = atomicAdd(&g_wptr[g_dst[e]], 1);
        g_csrc[pos] = g_src[e];
    }
}

// ---------------- bf16 tensor-core GEMM (R9: 128x128, BK=32, 4 stages) -----
#define GSTAGES 4
#define T_STRIDE 40
#define T_TILE   (128 * T_STRIDE)
#define STAGE_BYTES (T_TILE * 2)
#define GEMM_SMEM_BYTES (GSTAGES * 2 * STAGE_BYTES)    // 81920 B

__global__ __launch_bounds__(256, 2) void mma_gemm_k(
    const __nv_bfloat16* __restrict__ A, const __nv_bfloat16* __restrict__ Bt,
    __nv_bfloat16* __restrict__ C, int M, int N, int K,
    const float* __restrict__ a_s, const float* __restrict__ a_d, int H)
{
    extern __shared__ __align__(16) __nv_bfloat16 smem_h[];
    __nv_bfloat16* As = smem_h;
    __nv_bfloat16* Bs = smem_h + GSTAGES * T_TILE;

    const int t    = threadIdx.x;
    const int bm   = blockIdx.y * 128;
    const int bn   = blockIdx.x * 128;
    const int head = blockIdx.x;
    const int warp = t >> 5, lane = t & 31;
    const int wm   = (warp >> 2) * 64;
    const int wn   = (warp & 3) * 32;
    const int gid  = lane >> 2;
    const int tg   = lane & 3;

    const int kTiles = K >> 5;

    auto issue_tile = [&](int kt, int st) {
        __nv_bfloat16* as = As + st * T_TILE;
        __nv_bfloat16* bs = Bs + st * T_TILE;
#pragma unroll
        for (int q = 0; q < 2; q++) {
            int c = t + q * 256;
            int row = c >> 2, ce = (c & 3) * 8;
            int grow = bm + row;
            int sz = (grow < M) ? 16 : 0;
            if (grow >= M) grow = M - 1;
            cpa16(&as[row * T_STRIDE + ce], A  + (size_t)grow * K + kt * 32 + ce, sz);
            cpa16(&bs[row * T_STRIDE + ce], Bt + (size_t)(bn + row) * K + kt * 32 + ce, 16);
        }
    };

    const int q = lane >> 3, r = lane & 7;
    const uint32_t as0 = (uint32_t)__cvta_generic_to_shared(As);
    const uint32_t bs0 = (uint32_t)__cvta_generic_to_shared(Bs);
    uint32_t a_addr[4], b_addr[2];
#pragma unroll
    for (int mt = 0; mt < 4; mt++) {
        int row = wm + mt * 16 + r + ((q & 1) << 3);
        int col = (q >> 1) << 3;
        a_addr[mt] = as0 + (row * T_STRIDE + col) * 2;
    }
#pragma unroll
    for (int p = 0; p < 2; p++) {
        int row = wn + ((p * 2 + (q >> 1)) << 3) + r;
        int col = (q & 1) << 3;
        b_addr[p] = bs0 + (row * T_STRIDE + col) * 2;
    }

    float acc[4][4][4];
#pragma unroll
    for (int i = 0; i < 4; i++)
#pragma unroll
        for (int j = 0; j < 4; j++)
#pragma unroll
            for (int z = 0; z < 4; z++) acc[i][j][z] = 0.f;

#pragma unroll
    for (int s = 0; s < GSTAGES - 1; s++) {
        if (s < kTiles) issue_tile(s, s);
        cpa_commit();
    }

    for (int kt = 0; kt < kTiles; kt++) {
        cpa_wait<GSTAGES - 2>();
        __syncthreads();

        int nt = kt + GSTAGES - 1;
        if (nt < kTiles) issue_tile(nt, nt % GSTAGES);
        cpa_commit();

        const uint32_t soff = (uint32_t)((kt % GSTAGES) * STAGE_BYTES);

#pragma unroll
        for (int ks = 0; ks < 2; ks++) {
            const uint32_t ko = soff + ks * 32;
            uint32_t af[4][4], bf[4][2];
#pragma unroll
            for (int mt = 0; mt < 4; mt++)
                ldsm_x4(af[mt][0], af[mt][1], af[mt][2], af[mt][3], a_addr[mt] + ko);
#pragma unroll
            for (int p = 0; p < 2; p++)
                ldsm_x4(bf[p * 2][0], bf[p * 2][1], bf[p * 2 + 1][0], bf[p * 2 + 1][1],
                        b_addr[p] + ko);
#pragma unroll
            for (int mt = 0; mt < 4; mt++) {
#pragma unroll
                for (int ntile = 0; ntile < 4; ntile++) {
                    asm volatile(
                        "mma.sync.aligned.m16n8k16.row.col.f32.bf16.bf16.f32 "
                        "{%0,%1,%2,%3}, {%4,%5,%6,%7}, {%8,%9}, {%0,%1,%2,%3};\n"
                        : "+f"(acc[mt][ntile][0]), "+f"(acc[mt][ntile][1]),
                          "+f"(acc[mt][ntile][2]), "+f"(acc[mt][ntile][3])
                        : "r"(af[mt][0]), "r"(af[mt][1]), "r"(af[mt][2]), "r"(af[mt][3]),
                          "r"(bf[ntile][0]), "r"(bf[ntile][1]));
                }
            }
        }
        __syncthreads();
    }

    // ---- epilogue 1: store C tile (bf16) ----
#pragma unroll
    for (int mt = 0; mt < 4; mt++) {
        int r0 = bm + wm + mt * 16 + gid;
#pragma unroll
        for (int ntile = 0; ntile < 4; ntile++) {
            int c = bn + wn + ntile * 8 + 2 * tg;
            if (r0 < M) {
                __nv_bfloat162 p =
                    __floats2bfloat162_rn(acc[mt][ntile][0], acc[mt][ntile][1]);
                *(uint32_t*)&C[(size_t)r0 * N + c] = *(uint32_t*)&p;
            }
            if (r0 + 8 < M) {
                __nv_bfloat162 p =
                    __floats2bfloat162_rn(acc[mt][ntile][2], acc[mt][ntile][3]);
                *(uint32_t*)&C[(size_t)(r0 + 8) * N + c] = *(uint32_t*)&p;
            }
        }
    }

    // ---- epilogue 2: fused attention dots ----
    float* s_red = (float*)smem_h;
    s_red[t] = 0.f;
    __syncthreads();

    const float* asv = a_s + head * 128;
    const float* adv = a_d + head * 128;
    float csa[8], cda[8];
#pragma unroll
    for (int ntile = 0; ntile < 4; ntile++) {
        int c = wn + ntile * 8 + 2 * tg;
        csa[ntile * 2]     = asv[c];
        csa[ntile * 2 + 1] = asv[c + 1];
        cda[ntile * 2]     = adv[c];
        cda[ntile * 2 + 1] = adv[c + 1];
    }
#pragma unroll
    for (int mt = 0; mt < 4; mt++) {
#pragma unroll
        for (int half = 0; half < 2; half++) {
            float rs = 0.f, rd = 0.f;
#pragma unroll
            for (int ntile = 0; ntile < 4; ntile++) {
                rs = fmaf(acc[mt][ntile][half * 2],     csa[ntile * 2],     rs);
                rs = fmaf(acc[mt][ntile][half * 2 + 1], csa[ntile * 2 + 1], rs);
                rd = fmaf(acc[mt][ntile][half * 2],     cda[ntile * 2],     rd);
                rd = fmaf(acc[mt][ntile][half * 2 + 1], cda[ntile * 2 + 1], rd);
            }
            rs += __shfl_xor_sync(0xffffffffu, rs, 1);
            rs += __shfl_xor_sync(0xffffffffu, rs, 2);
            rd += __shfl_xor_sync(0xffffffffu, rd, 1);
            rd += __shfl_xor_sync(0xffffffffu, rd, 2);
            if (tg == 0) {
                int rl = wm + mt * 16 + half * 8 + gid;
                atomicAdd(&s_red[rl * 2],     rs);
                atomicAdd(&s_red[rl * 2 + 1], rd);
            }
        }
    }
    __syncthreads();
    if (t < 128 && bm + t < M) {
        g_als[(bm + t) * H + head] = s_red[t * 2];
        g_ald[(bm + t) * H + head] = s_red[t * 2 + 1];
    }
}

// ---------------- fused GAT softmax + aggregation, H=8 (R9 form) -----------
__global__ __launch_bounds__(256) void gat_fused8_k(
    const __nv_bfloat16* __restrict__ hw, const float* __restrict__ b,
    __nv_bfloat16* __restrict__ act)
{
    __shared__ float s_max[8], s_sum[8], s_ald[8];
    __shared__ float s_alpha[32][8];
    __shared__ int   s_srcs[32];

    const int d = blockIdx.x;
    const int t = threadIdx.x;
    const int beg = g_rowptr[d], deg = g_rowptr[d + 1] - beg;
    const int w = t >> 5, lane = t & 31;
    const int h = t & 7, j = t >> 3;

    if (t < 8) s_ald[t] = g_ald[d * 8 + t];

    {
        const float ald = g_ald[d * 8 + w];
        float m = -INFINITY;
        for (int i = lane; i < deg; i += 32) {
            int s = g_csrc[beg + i];
            float v = g_als[s * 8 + w] + ald;
            v = v > 0.f ? v : 0.2f * v;
            m = fmaxf(m, v);
        }
#pragma unroll
        for (int o = 16; o; o >>= 1)
            m = fmaxf(m, __shfl_xor_sync(0xffffffffu, m, o));
        float sum = 0.f;
        for (int i = lane; i < deg; i += 32) {
            int s = g_csrc[beg + i];
            float v = g_als[s * 8 + w] + ald;
            v = v > 0.f ? v : 0.2f * v;
            sum += __expf(v - m);
        }
#pragma unroll
        for (int o = 16; o; o >>= 1)
            sum += __shfl_xor_sync(0xffffffffu, sum, o);
        if (lane == 0) { s_max[w] = m; s_sum[w] = sum; }
    }
    __syncthreads();

    const int hh = t >> 5;
    const int ct = 4 * t;
    float4 a = make_float4(0.f, 0.f, 0.f, 0.f);
    for (int c0 = 0; c0 < deg; c0 += 32) {
        int cn = min(32, deg - c0);
        if (j < cn) {
            int s = g_csrc[beg + c0 + j];
            if (h == 0) s_srcs[j] = s;
            float v = g_als[s * 8 + h] + s_ald[h];
            v = v > 0.f ? v : 0.2f * v;
            s_alpha[j][h] = __expf(v - s_max[h]) / s_sum[h];
        }
        __syncthreads();
        for (int i = 0; i < cn; i++) {
            uint2 hv = *(const uint2*)(hw + (size_t)s_srcs[i] * 1024 + ct);
            float2 f0 = __bfloat1622float2(*(__nv_bfloat162*)&hv.x);
            float2 f1 = __bfloat1622float2(*(__nv_bfloat162*)&hv.y);
            const float al = s_alpha[i][hh];
            a.x = fmaf(f0.x, al, a.x);
            a.y = fmaf(f0.y, al, a.y);
            a.z = fmaf(f1.x, al, a.z);
            a.w = fmaf(f1.y, al, a.w);
        }
        __syncthreads();
    }

    const float4 bv = ((const float4*)b)[t];
    a.x = fmaxf(a.x + bv.x, 0.f);
    a.y = fmaxf(a.y + bv.y, 0.f);
    a.z = fmaxf(a.z + bv.z, 0.f);
    a.w = fmaxf(a.w + bv.w, 0.f);
    __nv_bfloat162 p0 = __floats2bfloat162_rn(a.x, a.y);
    __nv_bfloat162 p1 = __floats2bfloat162_rn(a.z, a.w);
    uint2 packed = make_uint2(*(uint32_t*)&p0, *(uint32_t*)&p1);
    *(uint2*)&act[(size_t)d * 1024 + ct] = packed;
}

// ---------------- fused GAT softmax + aggregation, H=1 (R9 form) -----------
__global__ __launch_bounds__(128) void gat_fused1_k(
    const __nv_bfloat16* __restrict__ hw, const float* __restrict__ b,
    float* __restrict__ out)
{
    __shared__ float red[128];
    __shared__ float s_alpha[32];
    __shared__ int   s_srcs[32];

    const int d = blockIdx.x;
    const int t = threadIdx.x;
    const int beg = g_rowptr[d], deg = g_rowptr[d + 1] - beg;
    const float ald = g_ald[d];

    float m = -INFINITY;
    for (int i = t; i < deg; i += 128) {
        float v = g_als[g_csrc[beg + i]] + ald;
        v = v > 0.f ? v : 0.2f * v;
        m = fmaxf(m, v);
    }
    red[t] = m; __syncthreads();
#pragma unroll
    for (int off = 64; off >= 1; off >>= 1) {
        if (t < off) red[t] = fmaxf(red[t], red[t + off]);
        __syncthreads();
    }
    const float mx = red[0];
    __syncthreads();

    float sum = 0.f;
    for (int i = t; i < deg; i += 128) {
        float v = g_als[g_csrc[beg + i]] + ald;
        v = v > 0.f ? v : 0.2f * v;
        sum += __expf(v - mx);
    }
    red[t] = sum; __syncthreads();
#pragma unroll
    for (int off = 64; off >= 1; off >>= 1) {
        if (t < off) red[t] += red[t + off];
        __syncthreads();
    }
    const float sm = red[0];
    __syncthreads();

    float acc = 0.f;
    for (int c0 = 0; c0 < deg; c0 += 32) {
        int cn = min(32, deg - c0);
        if (t < cn) {
            int s = g_csrc[beg + c0 + t];
            s_srcs[t] = s;
            float v = g_als[s] + ald;
            v = v > 0.f ? v : 0.2f * v;
            s_alpha[t] = __expf(v - mx) / sm;
        }
        __syncthreads();
        for (int i = 0; i < cn; i++)
            acc = fmaf(__bfloat162float(hw[(size_t)s_srcs[i] * 128 + t]),
                       s_alpha[i], acc);
        __syncthreads();
    }
    out[(size_t)d * 128 + t] = acc + b[t];
}

// ---------------- fused pair-MLP scorer ------------------------------------
__global__ __launch_bounds__(128) void mlp_k(
    const float* __restrict__ h3, const int* __restrict__ liq,
    const int* __restrict__ ing,
    const float* __restrict__ mw1, const float* __restrict__ mb1,
    const float* __restrict__ mw2, const float* __restrict__ mb2,
    const float* __restrict__ mw3, const float* __restrict__ mb3,
    float* __restrict__ outp)
{
    __shared__ float pair[256];
    __shared__ float z1[128];
    __shared__ float z2[64];
    int row = blockIdx.x, t = threadIdx.x;
    int L = liq[row], I = ing[row];
    pair[t]       = h3[(size_t)L * 128 + t];
    pair[128 + t] = h3[(size_t)I * 128 + t];
    __syncthreads();
    float acc = mb1[t];
#pragma unroll 8
    for (int i = 0; i < 256; i++) acc = fmaf(pair[i], mw1[i * 128 + t], acc);
    z1[t] = fmaxf(acc, 0.f);
    __syncthreads();
    if (t < 64) {
        float a2 = mb2[t];
#pragma unroll 8
        for (int i = 0; i < 128; i++) a2 = fmaf(z1[i], mw2[i * 64 + t], a2);
        z2[t] = fmaxf(a2, 0.f);
    }
    __syncthreads();
    if (t < 32) {
        float a3 = fmaf(z2[t], mw3[t], z2[t + 32] * mw3[t + 32]);
#pragma unroll
        for (int o = 16; o; o >>= 1) a3 += __shfl_down_sync(0xffffffffu, a3, o);
        if (t == 0) outp[row] = 1.f / (1.f + expf(-(a3 + mb3[0])));
    }
}

extern "C" void kernel_launch(void* const* d_in, const int* in_sizes, int n_in,
                              void* d_out, int out_size)
{
    const float* x   = (const float*)d_in[0];
    const int*   ei  = (const int*)d_in[1];
    const int*   liq = (const int*)d_in[2];
    const int*   ing = (const int*)d_in[3];
    const float* W1  = (const float*)d_in[4];
    const float* as1 = (const float*)d_in[5];
    const float* ad1 = (const float*)d_in[6];
    const float* b1  = (const float*)d_in[7];
    const float* W2  = (const float*)d_in[8];
    const float* as2 = (const float*)d_in[9];
    const float* ad2 = (const float*)d_in[10];
    const float* b2  = (const float*)d_in[11];
    const float* W3  = (const float*)d_in[12];
    const float* as3 = (const float*)d_in[13];
    const float* ad3 = (const float*)d_in[14];
    const float* b3  = (const float*)d_in[15];
    const float* mw1 = (const float*)d_in[16];
    const float* mb1 = (const float*)d_in[17];
    const float* mw2 = (const float*)d_in[18];
    const float* mb2 = (const float*)d_in[19];
    const float* mw3 = (const float*)d_in[20];
    const float* mb3 = (const float*)d_in[21];
    float* outp = (float*)d_out;

    cudaFuncSetAttribute(mma_gemm_k,
                         cudaFuncAttributeMaxDynamicSharedMemorySize,
                         GEMM_SMEM_BYTES);

    float* bufC;
    __nv_bfloat16 *hw, *act, *xb, *wt1, *wt2, *wt3;
    cudaGetSymbolAddress((void**)&hw,   g_hw);
    cudaGetSymbolAddress((void**)&bufC, g_bufC);
    cudaGetSymbolAddress((void**)&act,  g_act);
    cudaGetSymbolAddress((void**)&xb,   g_xb);
    cudaGetSymbolAddress((void**)&wt1,  g_wt1);
    cudaGetSymbolAddress((void**)&wt2,  g_wt2);
    cudaGetSymbolAddress((void**)&wt3,  g_wt3);

    // side streams + fork/join events (lazy one-time creation)
    static cudaStream_t s1 = nullptr, s2 = nullptr;
    static cudaEvent_t ev0 = nullptr, evCSR = nullptr, evW23 = nullptr;
    if (!s1) {
        cudaStreamCreateWithFlags(&s1, cudaStreamNonBlocking);
        cudaStreamCreateWithFlags(&s2, cudaStreamNonBlocking);
        cudaEventCreateWithFlags(&ev0,   cudaEventDisableTiming);
        cudaEventCreateWithFlags(&evCSR, cudaEventDisableTiming);
        cudaEventCreateWithFlags(&evW23, cudaEventDisableTiming);
    }

    // fork
    cudaEventRecord(ev0, 0);
    cudaStreamWaitEvent(s1, ev0, 0);
    cudaStreamWaitEvent(s2, ev0, 0);

    // s1: CSR chain
    zero_k<<<(N_NODES + 255) / 256, 256, 0, s1>>>();
    build_hist_k<<<(E_TOT + 255) / 256, 256, 0, s1>>>(ei);
    scan1_k<<<NBLK, 1024, 0, s1>>>();
    scan2_k<<<1, 32, 0, s1>>>();
    scan3_k<<<NBLK, 1024, 0, s1>>>();
    scatter_k<<<(E_TOT + 255) / 256, 256, 0, s1>>>();
    cudaEventRecord(evCSR, s1);

    // s2: W2/W3 conversion
    cvt_w23_k<<<(SEGW23 + 255) / 256, 256, 0, s2>>>(W2, W3);
    cudaEventRecord(evW23, s2);

    // main: x/W1 conversion -> layer-1 GEMM (independent of CSR and W2/W3)
    cvt_xw1_k<<<(SEGXW1 + 255) / 256, 256>>>(x, W1);

    dim3 grid8(8, (N_NODES + 127) / 128);
    dim3 grid1(1, (N_NODES + 127) / 128);

    mma_gemm_k<<<grid8, 256, GEMM_SMEM_BYTES>>>(xb, wt1, hw, N_NODES, 1024, 64,
                                                as1, ad1, 8);

    // join: aggregation needs CSR; layer-2 GEMM needs wt2
    cudaStreamWaitEvent(0, evCSR, 0);
    gat_fused8_k<<<N_NODES, 256>>>(hw, b1, act);

    cudaStreamWaitEvent(0, evW23, 0);
    mma_gemm_k<<<grid8, 256, GEMM_SMEM_BYTES>>>(act, wt2, hw, N_NODES, 1024, 1024,
                                                as2, ad2, 8);
    gat_fused8_k<<<N_NODES, 256>>>(hw, b2, act);

    mma_gemm_k<<<grid1, 256, GEMM_SMEM_BYTES>>>(act, wt3, hw, N_NODES, 128, 1024,
                                                as3, ad3, 1);
    gat_fused1_k<<<N_NODES, 128>>>(hw, b3, bufC);

    mlp_k<<<4096, 128>>>(bufC, liq, ing, mw1, mb1, mw2, mb2, mw3, mb3, outp);
}